// round 2
// baseline (speedup 1.0000x reference)
#include <cuda_runtime.h>
#include <math.h>

// Problem constants
#define BB   8
#define CC   512
#define LL   4096
#define HH   8
#define TK   256
#define MM   2048
#define CHD  64
#define BLROWS (BB*LL)   // 32768

// ---------------- scratch (device globals; no allocation allowed) ----------
__device__ float g_xt  [(size_t)BB*LL*CC];      // x transposed (B,L,C)
__device__ float g_q   [(size_t)BB*LL*CC];      // Q raw -> QN (LN + l2n) in place
__device__ float g_kv  [(size_t)BB*LL*2*CC];    // KV raw
__device__ float g_kn  [(size_t)BB*LL*CC];      // K LN + l2n
__device__ float g_vt  [(size_t)BB*LL*CC];      // V LN
__device__ float g_pp  [(size_t)BB*32*CC];      // probe partials
__device__ float g_probe[BB*CC];
__device__ float g_score[BB*HH*LL];
__device__ int   g_idx [BB*HH*TK];
__device__ float g_kc  [(size_t)BB*TK*CC];
__device__ float g_vc  [(size_t)BB*TK*CC];
__device__ float g_kp  [(size_t)BB*TK*CC];
__device__ float g_vp  [(size_t)BB*TK*CC];
__device__ float g_qp  [(size_t)BB*LL*CC];
__device__ float g_ao  [(size_t)BB*LL*CC];
__device__ float g_a   [(size_t)BB*LL*CC];
__device__ float g_h1  [(size_t)BB*LL*MM];
__device__ float g_h2  [(size_t)BB*LL*CC];

// ---------------- transpose (B,C,L) -> (B,L,C) -----------------------------
__global__ void k_transpose_in(const float* __restrict__ X, float* __restrict__ Y) {
    __shared__ float tile[32][33];
    int b  = blockIdx.z;
    int l0 = blockIdx.x << 5, c0 = blockIdx.y << 5;
    int tx = threadIdx.x, ty = threadIdx.y;
    const float* Xb = X + (size_t)b*CC*LL;
    #pragma unroll
    for (int i = ty; i < 32; i += 8)
        tile[i][tx] = Xb[(size_t)(c0+i)*LL + l0 + tx];
    __syncthreads();
    float* Yb = Y + (size_t)b*LL*CC;
    #pragma unroll
    for (int i = ty; i < 32; i += 8)
        Yb[(size_t)(l0+i)*CC + c0 + tx] = tile[tx][i];
}

// ---------------- out = transpose(H + A), (B,L,C) -> (B,C,L) ---------------
__global__ void k_add_transpose_out(const float* __restrict__ Hh, const float* __restrict__ A,
                                    float* __restrict__ OUT) {
    __shared__ float tile[32][33];
    int b  = blockIdx.z;
    int l0 = blockIdx.x << 5, c0 = blockIdx.y << 5;
    int tx = threadIdx.x, ty = threadIdx.y;
    const float* Hb = Hh + (size_t)b*LL*CC;
    const float* Ab = A  + (size_t)b*LL*CC;
    #pragma unroll
    for (int i = ty; i < 32; i += 8) {
        size_t o = (size_t)(l0+i)*CC + c0 + tx;
        tile[i][tx] = Hb[o] + Ab[o];
    }
    __syncthreads();
    float* Ob = OUT + (size_t)b*CC*LL;
    #pragma unroll
    for (int i = ty; i < 32; i += 8)
        Ob[(size_t)(c0+i)*LL + l0 + tx] = tile[tx][i];
}

// ---------------- generic GEMM: Y(n,N) = X(n,K) @ W(N,K)^T + bias ----------
// 128x128 block tile, BK=8, 256 threads, 8x8 per thread.
// rows = tr + 16*i, cols = tc + 16*j  (conflict-free smem B reads).
__global__ void k_gemm_bias(const float* __restrict__ X, const float* __restrict__ W,
                            const float* __restrict__ bias, float* __restrict__ Y,
                            int n, int N, int K) {
    __shared__ float As[8][132];
    __shared__ float Bs[8][132];
    const int tid = threadIdx.x;
    const int bm = blockIdx.y << 7;
    const int bn = blockIdx.x << 7;
    float acc[8][8];
    #pragma unroll
    for (int i = 0; i < 8; i++)
        #pragma unroll
        for (int j = 0; j < 8; j++) acc[i][j] = 0.f;

    const int lrow = tid >> 1;           // 0..127
    const int lk   = (tid & 1) << 2;     // 0 or 4
    const float* xg = X + (size_t)(bm + lrow)*K + lk;
    const float* wg = W + (size_t)(bn + lrow)*K + lk;
    const int tr = tid >> 4;             // 0..15
    const int tc = tid & 15;             // 0..15

    for (int k0 = 0; k0 < K; k0 += 8) {
        float4 av = *(const float4*)(xg + k0);
        float4 bv = *(const float4*)(wg + k0);
        As[lk+0][lrow] = av.x; As[lk+1][lrow] = av.y;
        As[lk+2][lrow] = av.z; As[lk+3][lrow] = av.w;
        Bs[lk+0][lrow] = bv.x; Bs[lk+1][lrow] = bv.y;
        Bs[lk+2][lrow] = bv.z; Bs[lk+3][lrow] = bv.w;
        __syncthreads();
        #pragma unroll
        for (int kk = 0; kk < 8; kk++) {
            float a[8], bvv[8];
            #pragma unroll
            for (int i = 0; i < 8; i++) a[i]   = As[kk][tr + (i<<4)];
            #pragma unroll
            for (int j = 0; j < 8; j++) bvv[j] = Bs[kk][tc + (j<<4)];
            #pragma unroll
            for (int i = 0; i < 8; i++)
                #pragma unroll
                for (int j = 0; j < 8; j++)
                    acc[i][j] += a[i]*bvv[j];
        }
        __syncthreads();
    }
    #pragma unroll
    for (int j = 0; j < 8; j++) {
        float bj = bias[bn + tc + (j<<4)];
        #pragma unroll
        for (int i = 0; i < 8; i++)
            Y[(size_t)(bm + tr + (i<<4))*N + bn + tc + (j<<4)] = acc[i][j] + bj;
    }
}

// ---------------- row LayerNorm with fused epilogues ------------------------
// mode 0: plain LN ; 1: LN + per-64-chunk l2n (Wd==512) ; 2: LN*gamma + resid
// mode 3: LN + relu.  One block (256 threads) per row; thread t owns
// contiguous [t*E, t*E+E) with E = Wd/256 (so warp == head chunk when Wd=512).
__global__ void k_ln(const float* __restrict__ in, int ld_in,
                     float* __restrict__ out,
                     const float* __restrict__ gam, const float* __restrict__ bet,
                     int Wd, int mode, const float* __restrict__ gamma_p,
                     const float* __restrict__ resid) {
    int row = blockIdx.x;
    int tid = threadIdx.x;
    int E = Wd >> 8;                      // 2 or 8
    const float* xr = in + (size_t)row*ld_in + (size_t)tid*E;
    float v[8];
    float s = 0.f, s2 = 0.f;
    for (int i = 0; i < E; i++) { v[i] = xr[i]; s += v[i]; s2 += v[i]*v[i]; }

    __shared__ float rs[256], rs2[256];
    rs[tid] = s; rs2[tid] = s2;
    __syncthreads();
    for (int off = 128; off > 0; off >>= 1) {
        if (tid < off) { rs[tid] += rs[tid+off]; rs2[tid] += rs2[tid+off]; }
        __syncthreads();
    }
    float mu  = rs[0] / (float)Wd;
    float var = rs2[0] / (float)Wd - mu*mu;
    float rstd = rsqrtf(var + 1e-5f);

    float y[8];
    for (int i = 0; i < E; i++) {
        int c = tid*E + i;
        y[i] = (v[i] - mu)*rstd*gam[c] + bet[c];
    }
    if (mode == 1) {   // l2n over 64-ch head chunk == one warp (Wd=512, E=2)
        float qq = y[0]*y[0] + y[1]*y[1];
        #pragma unroll
        for (int o = 16; o > 0; o >>= 1) qq += __shfl_xor_sync(0xffffffffu, qq, o);
        float sc = 1.0f / fmaxf(sqrtf(qq), 1e-12f);
        y[0] *= sc; y[1] *= sc;
    } else if (mode == 2) {
        float gsc = gamma_p[0];
        const float* rr = resid + (size_t)row*Wd + (size_t)tid*E;
        for (int i = 0; i < E; i++) y[i] = y[i]*gsc + rr[i];
    } else if (mode == 3) {
        for (int i = 0; i < E; i++) y[i] = fmaxf(y[i], 0.f);
    }
    float* yr = out + (size_t)row*Wd + (size_t)tid*E;
    for (int i = 0; i < E; i++) yr[i] = y[i];
}

// ---------------- q_probe = sum over L of QN --------------------------------
__global__ void k_probe_partial(const float* __restrict__ QN, float* __restrict__ part) {
    int b = blockIdx.x, ch = blockIdx.y;
    int c = threadIdx.x;                   // 512
    const int CHUNK = LL / 32;             // 128
    const float* p = QN + ((size_t)b*LL + (size_t)ch*CHUNK)*CC + c;
    float s = 0.f;
    for (int i = 0; i < CHUNK; i++) s += p[(size_t)i*CC];
    part[((size_t)b*32 + ch)*CC + c] = s;
}
__global__ void k_probe_reduce(const float* __restrict__ part, float* __restrict__ probe) {
    int b = blockIdx.x; int c = threadIdx.x;
    float s = 0.f;
    for (int ch = 0; ch < 32; ch++) s += part[((size_t)b*32 + ch)*CC + c];
    probe[b*CC + c] = s;
}

// ---------------- score[b,h,l] = probe . (|k|+k) -----------------------------
__global__ void k_score(const float* __restrict__ KN, const float* __restrict__ probe,
                        float* __restrict__ score) {
    int gw   = (blockIdx.x * blockDim.x + threadIdx.x) >> 5;   // (b,l)
    int lane = threadIdx.x & 31;
    if (gw >= BB*LL) return;
    int b = gw >> 12;          // /4096
    int l = gw & (LL-1);
    const float* krow = KN + (size_t)gw*CC;
    const float* pr   = probe + b*CC;
    int c0 = lane << 4;
    float s = 0.f;
    #pragma unroll
    for (int j = 0; j < 16; j += 4) {
        float4 k4 = *(const float4*)(krow + c0 + j);
        float4 p4 = *(const float4*)(pr   + c0 + j);
        s += p4.x*(fabsf(k4.x)+k4.x) + p4.y*(fabsf(k4.y)+k4.y)
           + p4.z*(fabsf(k4.z)+k4.z) + p4.w*(fabsf(k4.w)+k4.w);
    }
    s += __shfl_xor_sync(0xffffffffu, s, 1);
    s += __shfl_xor_sync(0xffffffffu, s, 2);
    if ((lane & 3) == 0) {
        int h = lane >> 2;
        score[((size_t)(b*HH + h))*LL + l] = s;
    }
}

// ---------------- exact top-k via in-smem bitonic sort -----------------------
__global__ void k_topk(const float* __restrict__ score, int* __restrict__ idx) {
    __shared__ unsigned long long keys[LL];   // 32 KB
    int bh = blockIdx.x;
    const float* s = score + (size_t)bh*LL;
    for (int i = threadIdx.x; i < LL; i += blockDim.x) {
        unsigned u = __float_as_uint(s[i]);
        u = (u & 0x80000000u) ? ~u : (u | 0x80000000u);   // monotone
        keys[i] = ((unsigned long long)u << 32) | (unsigned)(LL-1-i); // tie: lower i wins
    }
    __syncthreads();
    for (int k = 2; k <= LL; k <<= 1) {
        for (int j = k >> 1; j > 0; j >>= 1) {
            for (int i = threadIdx.x; i < LL; i += blockDim.x) {
                int ixj = i ^ j;
                if (ixj > i) {
                    unsigned long long a = keys[i], c = keys[ixj];
                    bool desc = (i & k) == 0;
                    if (desc ? (a < c) : (a > c)) { keys[i] = c; keys[ixj] = a; }
                }
            }
            __syncthreads();
        }
    }
    for (int t = threadIdx.x; t < TK; t += blockDim.x)
        idx[bh*TK + t] = (LL-1) - (int)(unsigned)(keys[t] & 0xffffffffu);
}

// ---------------- gather selected K/V rows per head --------------------------
__global__ void k_gather(const float* __restrict__ KN, const float* __restrict__ VT,
                         const int* __restrict__ idx,
                         float* __restrict__ KC, float* __restrict__ VC) {
    int bt = blockIdx.x;                  // b*TK + t
    int b = bt / TK, t = bt % TK;
    int c = threadIdx.x;                  // 512
    int h = c >> 6;
    int l = idx[(b*HH + h)*TK + t];
    size_t src = ((size_t)b*LL + l)*CC + c;
    size_t dst = (size_t)bt*CC + c;
    KC[dst] = KN[src];
    VC[dst] = VT[src];
}

// ---------------- attention: per (b,h,64-query tile), online softmax ---------
// 256 threads = 64 groups x 4 lanes; each lane owns 16 channels of its query.
__global__ void k_attn(const float* __restrict__ QP, const float* __restrict__ KP,
                       const float* __restrict__ VP, const float* __restrict__ bk,
                       const float* __restrict__ bv, float* __restrict__ AO) {
    __shared__ float Ks[64][64];
    __shared__ float Vs[64][64];
    int bh = blockIdx.y;
    int b = bh >> 3, h = bh & 7;
    int l0 = blockIdx.x << 6;
    int tid = threadIdx.x;
    int g = tid >> 2;
    int r = tid & 3;
    int l = l0 + g;
    const int cbase = h*CHD + r*16;

    float q[16];
    const float* qrow = QP + ((size_t)b*LL + l)*CC + cbase;
    #pragma unroll
    for (int i = 0; i < 16; i++) q[i] = qrow[i];

    float acc[16];
    #pragma unroll
    for (int i = 0; i < 16; i++) acc[i] = 0.f;
    float m = -1e30f, denom = 0.f;

    for (int kc0 = 0; kc0 < TK; kc0 += 64) {
        for (int i = tid; i < 64*64; i += 256) {
            int rowk = i >> 6, cc = i & 63;
            size_t src = ((size_t)b*TK + kc0 + rowk)*CC + h*CHD + cc;
            Ks[rowk][cc] = KP[src];
            Vs[rowk][cc] = VP[src];
        }
        __syncthreads();
        for (int j = 0; j < 64; j++) {
            float part = 0.f;
            #pragma unroll
            for (int i = 0; i < 16; i++) part += q[i]*Ks[j][r*16 + i];
            part += __shfl_xor_sync(0xffffffffu, part, 1);
            part += __shfl_xor_sync(0xffffffffu, part, 2);
            float sc = part * 0.125f;
            if (sc > m) {
                float corr = __expf(m - sc);
                denom *= corr;
                #pragma unroll
                for (int i = 0; i < 16; i++) acc[i] *= corr;
                m = sc;
            }
            float p = __expf(sc - m);
            denom += p;
            #pragma unroll
            for (int i = 0; i < 16; i++) acc[i] += p*Vs[j][r*16 + i];
        }
        __syncthreads();
    }
    // extra key 256: raw bias_k / bias_v
    {
        float part = 0.f;
        #pragma unroll
        for (int i = 0; i < 16; i++) part += q[i]*bk[cbase + i];
        part += __shfl_xor_sync(0xffffffffu, part, 1);
        part += __shfl_xor_sync(0xffffffffu, part, 2);
        float sc = part * 0.125f;
        if (sc > m) {
            float corr = __expf(m - sc);
            denom *= corr;
            #pragma unroll
            for (int i = 0; i < 16; i++) acc[i] *= corr;
            m = sc;
        }
        float p = __expf(sc - m);
        denom += p;
        #pragma unroll
        for (int i = 0; i < 16; i++) acc[i] += p*bv[cbase + i];
    }
    float inv = 1.f / denom;
    float* orow = AO + ((size_t)b*LL + l)*CC + cbase;
    #pragma unroll
    for (int i = 0; i < 16; i++) orow[i] = acc[i]*inv;
}

// ---------------------------- launcher ---------------------------------------
extern "C" void kernel_launch(void* const* d_in, const int* in_sizes, int n_in,
                              void* d_out, int out_size) {
    const float* x         = (const float*)d_in[0];
    const float* q_conv_w  = (const float*)d_in[1];
    const float* q_conv_b  = (const float*)d_in[2];
    const float* q_ln_g    = (const float*)d_in[3];
    const float* q_ln_b    = (const float*)d_in[4];
    const float* kv_conv_w = (const float*)d_in[5];
    const float* kv_conv_b = (const float*)d_in[6];
    const float* k_ln_g    = (const float*)d_in[7];
    const float* k_ln_b    = (const float*)d_in[8];
    const float* v_ln_g    = (const float*)d_in[9];
    const float* v_ln_b    = (const float*)d_in[10];
    const float* in_proj_w = (const float*)d_in[11];
    const float* in_proj_b = (const float*)d_in[12];
    const float* bias_k    = (const float*)d_in[13];
    const float* bias_v    = (const float*)d_in[14];
    const float* out_proj_w= (const float*)d_in[15];
    const float* out_proj_b= (const float*)d_in[16];
    const float* attn_ln_g = (const float*)d_in[17];
    const float* attn_ln_b = (const float*)d_in[18];
    const float* gamma     = (const float*)d_in[19];
    const float* w1        = (const float*)d_in[20];
    const float* b1        = (const float*)d_in[21];
    const float* n1_g      = (const float*)d_in[22];
    const float* n1_b      = (const float*)d_in[23];
    const float* w2        = (const float*)d_in[24];
    const float* b2        = (const float*)d_in[25];
    const float* n2_g      = (const float*)d_in[26];
    const float* n2_b      = (const float*)d_in[27];
    float* out = (float*)d_out;

    float *xt, *q, *kv, *kn, *vt, *pp, *probe, *score, *kc, *vc, *kp, *vp, *qp, *ao, *a, *h1, *h2;
    int* idx;
    cudaGetSymbolAddress((void**)&xt,   g_xt);
    cudaGetSymbolAddress((void**)&q,    g_q);
    cudaGetSymbolAddress((void**)&kv,   g_kv);
    cudaGetSymbolAddress((void**)&kn,   g_kn);
    cudaGetSymbolAddress((void**)&vt,   g_vt);
    cudaGetSymbolAddress((void**)&pp,   g_pp);
    cudaGetSymbolAddress((void**)&probe,g_probe);
    cudaGetSymbolAddress((void**)&score,g_score);
    cudaGetSymbolAddress((void**)&idx,  g_idx);
    cudaGetSymbolAddress((void**)&kc,   g_kc);
    cudaGetSymbolAddress((void**)&vc,   g_vc);
    cudaGetSymbolAddress((void**)&kp,   g_kp);
    cudaGetSymbolAddress((void**)&vp,   g_vp);
    cudaGetSymbolAddress((void**)&qp,   g_qp);
    cudaGetSymbolAddress((void**)&ao,   g_ao);
    cudaGetSymbolAddress((void**)&a,    g_a);
    cudaGetSymbolAddress((void**)&h1,   g_h1);
    cudaGetSymbolAddress((void**)&h2,   g_h2);

    dim3 tgrid(LL/32, CC/32, BB), tblk(32, 8);
    k_transpose_in<<<tgrid, tblk>>>(x, xt);

    // Q / KV projections
    k_gemm_bias<<<dim3(CC/128,   BLROWS/128), 256>>>(xt, q_conv_w,  q_conv_b,  q,  BLROWS, CC,   CC);
    k_gemm_bias<<<dim3(2*CC/128, BLROWS/128), 256>>>(xt, kv_conv_w, kv_conv_b, kv, BLROWS, 2*CC, CC);

    // LayerNorms (+l2n for Q,K)
    k_ln<<<BLROWS, 256>>>(q,        CC,    q,  q_ln_g, q_ln_b, CC, 1, nullptr, nullptr);
    k_ln<<<BLROWS, 256>>>(kv,       2*CC,  kn, k_ln_g, k_ln_b, CC, 1, nullptr, nullptr);
    k_ln<<<BLROWS, 256>>>(kv + CC,  2*CC,  vt, v_ln_g, v_ln_b, CC, 0, nullptr, nullptr);

    // probe, score, top-k, gather
    k_probe_partial<<<dim3(BB, 32), CC>>>(q, pp);
    k_probe_reduce<<<BB, CC>>>(pp, probe);
    k_score<<<(BB*LL*32)/256, 256>>>(kn, probe, score);
    k_topk<<<BB*HH, 512>>>(score, idx);
    k_gather<<<BB*TK, CC>>>(kn, vt, idx, kc, vc);

    // in_proj: qp on all queries, kp/vp on gathered rows
    k_gemm_bias<<<dim3(CC/128, BLROWS/128),   256>>>(q,  in_proj_w,            in_proj_b,        qp, BLROWS, CC, CC);
    k_gemm_bias<<<dim3(CC/128, (BB*TK)/128),  256>>>(kc, in_proj_w + CC*CC,    in_proj_b + CC,   kp, BB*TK,  CC, CC);
    k_gemm_bias<<<dim3(CC/128, (BB*TK)/128),  256>>>(vc, in_proj_w + 2*CC*CC,  in_proj_b + 2*CC, vp, BB*TK,  CC, CC);

    // attention (257 keys: 256 selected + bias key)
    k_attn<<<dim3(LL/64, BB*HH), 256>>>(qp, kp, vp, bias_k, bias_v, ao);

    // out_proj -> h2(temp), attn LN * gamma + x residual -> a
    k_gemm_bias<<<dim3(CC/128, BLROWS/128), 256>>>(ao, out_proj_w, out_proj_b, h2, BLROWS, CC, CC);
    k_ln<<<BLROWS, 256>>>(h2, CC, a, attn_ln_g, attn_ln_b, CC, 2, gamma, xt);

    // FFN
    k_gemm_bias<<<dim3(MM/128, BLROWS/128), 256>>>(a,  w1, b1, h1, BLROWS, MM, CC);
    k_ln<<<BLROWS, 256>>>(h1, MM, h1, n1_g, n1_b, MM, 3, nullptr, nullptr);
    k_gemm_bias<<<dim3(CC/128, BLROWS/128), 256>>>(h1, w2, b2, h2, BLROWS, CC, MM);
    k_ln<<<BLROWS, 256>>>(h2, CC, h2, n2_g, n2_b, CC, 3, nullptr, nullptr);

    // out = transpose(h2 + a)
    k_add_transpose_out<<<tgrid, tblk>>>(h2, a, out);
}

// round 4
// speedup vs baseline: 1.6781x; 1.6781x over previous
#include <cuda_runtime.h>
#include <cuda_bf16.h>
#include <math.h>
#include <stdint.h>

// Problem constants
#define BB   8
#define CC   512
#define LL   4096
#define HH   8
#define TK   256
#define MM   2048
#define CHD  64
#define BLROWS (BB*LL)   // 32768

// ---------------- scratch (device globals; no allocation allowed) ----------
__device__ __align__(16) float g_xt  [(size_t)BB*LL*CC];
__device__ __align__(16) float g_q   [(size_t)BB*LL*CC];
__device__ __align__(16) float g_kv  [(size_t)BB*LL*2*CC];
__device__ __align__(16) float g_kn  [(size_t)BB*LL*CC];
__device__ __align__(16) float g_vt  [(size_t)BB*LL*CC];
__device__ __align__(16) float g_pp  [(size_t)BB*32*CC];
__device__ __align__(16) float g_probe[BB*CC];
__device__ __align__(16) float g_score[BB*HH*LL];
__device__ __align__(16) int   g_idx [BB*HH*TK];
__device__ __align__(16) float g_kp  [(size_t)BB*TK*CC];
__device__ __align__(16) float g_vp  [(size_t)BB*TK*CC];
__device__ __align__(16) float g_qp  [(size_t)BB*LL*CC];
__device__ __align__(16) float g_a   [(size_t)BB*LL*CC];
__device__ __align__(16) float g_h1  [(size_t)BB*LL*MM];
__device__ __align__(16) float g_h2  [(size_t)BB*LL*CC];

// bf16 hi/lo split activations
__device__ __align__(16) __nv_bfloat16 g_xt_h[(size_t)BB*LL*CC];
__device__ __align__(16) __nv_bfloat16 g_xt_l[(size_t)BB*LL*CC];
__device__ __align__(16) __nv_bfloat16 g_q_h [(size_t)BB*LL*CC];
__device__ __align__(16) __nv_bfloat16 g_q_l [(size_t)BB*LL*CC];
__device__ __align__(16) __nv_bfloat16 g_kc_h[(size_t)BB*TK*CC];
__device__ __align__(16) __nv_bfloat16 g_kc_l[(size_t)BB*TK*CC];
__device__ __align__(16) __nv_bfloat16 g_vc_h[(size_t)BB*TK*CC];
__device__ __align__(16) __nv_bfloat16 g_vc_l[(size_t)BB*TK*CC];
__device__ __align__(16) __nv_bfloat16 g_ao_h[(size_t)BB*LL*CC];
__device__ __align__(16) __nv_bfloat16 g_ao_l[(size_t)BB*LL*CC];
__device__ __align__(16) __nv_bfloat16 g_a_h [(size_t)BB*LL*CC];
__device__ __align__(16) __nv_bfloat16 g_a_l [(size_t)BB*LL*CC];
__device__ __align__(16) __nv_bfloat16 g_h1_h[(size_t)BB*LL*MM];
__device__ __align__(16) __nv_bfloat16 g_h1_l[(size_t)BB*LL*MM];

// bf16 hi/lo weights
__device__ __align__(16) __nv_bfloat16 g_wq_h [CC*CC],    g_wq_l [CC*CC];
__device__ __align__(16) __nv_bfloat16 g_wkv_h[2*CC*CC],  g_wkv_l[2*CC*CC];
__device__ __align__(16) __nv_bfloat16 g_win_h[3*CC*CC],  g_win_l[3*CC*CC];
__device__ __align__(16) __nv_bfloat16 g_wo_h [CC*CC],    g_wo_l [CC*CC];
__device__ __align__(16) __nv_bfloat16 g_w1_h [MM*CC],    g_w1_l [MM*CC];
__device__ __align__(16) __nv_bfloat16 g_w2_h [CC*MM],    g_w2_l [CC*MM];

// ================= helpers ===================================================
static __device__ __forceinline__ uint32_t smem_u32(const void* p) {
    uint32_t a;
    asm("{ .reg .u64 t; cvta.to.shared.u64 t, %1; cvt.u32.u64 %0, t; }"
        : "=r"(a) : "l"(p));
    return a;
}
static __device__ __forceinline__ void split_bf16(float v, __nv_bfloat16& h, __nv_bfloat16& l) {
    h = __float2bfloat16(v);
    l = __float2bfloat16(v - __bfloat162float(h));
}
static __device__ __forceinline__ void ldmA(uint32_t* r, uint32_t addr) {
    asm volatile("ldmatrix.sync.aligned.m8n8.x4.shared.b16 {%0,%1,%2,%3}, [%4];"
                 : "=r"(r[0]), "=r"(r[1]), "=r"(r[2]), "=r"(r[3]) : "r"(addr));
}
static __device__ __forceinline__ void ldmB(uint32_t* r, uint32_t addr) {
    asm volatile("ldmatrix.sync.aligned.m8n8.x2.shared.b16 {%0,%1}, [%2];"
                 : "=r"(r[0]), "=r"(r[1]) : "r"(addr));
}
static __device__ __forceinline__ void mma16816(float* d, const uint32_t* a, const uint32_t* b) {
    asm volatile(
        "mma.sync.aligned.m16n8k16.row.col.f32.bf16.bf16.f32 "
        "{%0,%1,%2,%3}, {%4,%5,%6,%7}, {%8,%9}, {%0,%1,%2,%3};"
        : "+f"(d[0]), "+f"(d[1]), "+f"(d[2]), "+f"(d[3])
        : "r"(a[0]), "r"(a[1]), "r"(a[2]), "r"(a[3]), "r"(b[0]), "r"(b[1]));
}
static __device__ __forceinline__ void cpasync16(uint32_t saddr, const void* gaddr) {
    asm volatile("cp.async.cg.shared.global [%0], [%1], 16;"
                 :: "r"(saddr), "l"(gaddr) : "memory");
}

// ================= tensor-core GEMM via mma.sync ============================
// Y(row,col) = sum_K Xhi/lo(row,K) * Whi/lo(col,K) + bias[col]
// Tile 128x128, BK=32, 8 warps (4 M x 2 N), warp tile 32x64.
// bf16 3-product split: D += Ah*Bh + Ah*Bl + Al*Bh.
// smem: 2 stages x 4 matrices x 128 rows x 80B (padded, conflict-free ldmatrix).
#define MTX_BYTES 10240          // 128 * 80
#define STAGE_BYTES 40960        // 4 * MTX_BYTES
__global__ void __launch_bounds__(256, 1) k_gemm_mma(
    const __nv_bfloat16* __restrict__ Ah, const __nv_bfloat16* __restrict__ Al,
    const __nv_bfloat16* __restrict__ Bh, const __nv_bfloat16* __restrict__ Bl,
    const float* __restrict__ bias, float* __restrict__ Y, int N, int K)
{
    extern __shared__ __align__(128) char smem[];
    const uint32_t sb = smem_u32(smem);
    const int tid  = threadIdx.x;
    const int wid  = tid >> 5, lane = tid & 31;
    const int wm   = wid & 3;              // warp M 0..3 (32 rows each)
    const int wn   = wid >> 2;             // warp N 0..1 (64 cols each)
    const int bm = blockIdx.y << 7, bn = blockIdx.x << 7;

    const __nv_bfloat16* srcs[4] = {Ah, Al, Bh, Bl};
    const int nch = K >> 5;                // chunks of BK=32

    float acc[2][8][4];
    #pragma unroll
    for (int m = 0; m < 2; m++)
        #pragma unroll
        for (int n = 0; n < 8; n++)
            #pragma unroll
            for (int v = 0; v < 4; v++) acc[m][n][v] = 0.f;

    // ---- async load of one chunk into stage s ----
    auto load_chunk = [&](int ck, int s) {
        const int k0 = ck << 5;
        const uint32_t so = sb + s * STAGE_BYTES;
        #pragma unroll
        for (int i = 0; i < 8; i++) {
            int idx  = tid + (i << 8);           // 0..2047
            int mtx  = idx >> 9;                 // 0..3
            int unit = idx & 511;                // 16B unit within matrix
            int row  = unit >> 2, seg = unit & 3;
            int rb   = (mtx < 2) ? bm : bn;
            const __nv_bfloat16* g = srcs[mtx] + (size_t)(rb + row) * K + k0 + (seg << 3);
            cpasync16(so + mtx * MTX_BYTES + row * 80 + (seg << 4), g);
        }
        asm volatile("cp.async.commit_group;" ::: "memory");
    };

    load_chunk(0, 0);

    // precomputed ldmatrix lane offsets
    const uint32_t aRow = (lane & 7) + ((lane >> 3) & 1) * 8;   // row within 16
    const uint32_t aKof = (lane >> 4) * 8;                      // 0 or 8
    const uint32_t bRow = (lane & 7);
    const uint32_t bKof = ((lane >> 3) & 1) * 8;

    for (int ck = 0; ck < nch; ck++) {
        const int s = ck & 1;
        if (ck + 1 < nch) {
            load_chunk(ck + 1, s ^ 1);
            asm volatile("cp.async.wait_group 1;" ::: "memory");
        } else {
            asm volatile("cp.async.wait_group 0;" ::: "memory");
        }
        __syncthreads();

        const uint32_t so  = sb + s * STAGE_BYTES;
        const uint32_t sAh = so;
        const uint32_t sAl = so + MTX_BYTES;
        const uint32_t sBh = so + 2 * MTX_BYTES;
        const uint32_t sBl = so + 3 * MTX_BYTES;

        #pragma unroll
        for (int ks = 0; ks < 2; ks++) {        // two k16 steps per chunk
            uint32_t ah[2][4], al[2][4];
            #pragma unroll
            for (int mf = 0; mf < 2; mf++) {
                uint32_t row = wm * 32 + mf * 16 + aRow;
                uint32_t off = row * 80 + (aKof + ks * 16) * 2;
                ldmA(ah[mf], sAh + off);
                ldmA(al[mf], sAl + off);
            }
            #pragma unroll
            for (int nt = 0; nt < 8; nt++) {
                uint32_t row = wn * 64 + nt * 8 + bRow;
                uint32_t off = row * 80 + (bKof + ks * 16) * 2;
                uint32_t bh[2], bl[2];
                ldmB(bh, sBh + off);
                ldmB(bl, sBl + off);
                #pragma unroll
                for (int mf = 0; mf < 2; mf++) {
                    mma16816(acc[mf][nt], ah[mf], bh);
                    mma16816(acc[mf][nt], ah[mf], bl);
                    mma16816(acc[mf][nt], al[mf], bh);
                }
            }
        }
        __syncthreads();
    }

    // ---- epilogue: bias add, direct fp32 stores ----
    const int r  = lane >> 2;
    const int c2 = (lane & 3) << 1;
    #pragma unroll
    for (int mf = 0; mf < 2; mf++) {
        const int gm = bm + wm * 32 + mf * 16;
        #pragma unroll
        for (int nt = 0; nt < 8; nt++) {
            const int gn = bn + wn * 64 + nt * 8 + c2;
            float bx = bias[gn], by = bias[gn + 1];
            float2 v0 = make_float2(acc[mf][nt][0] + bx, acc[mf][nt][1] + by);
            float2 v1 = make_float2(acc[mf][nt][2] + bx, acc[mf][nt][3] + by);
            *(float2*)(Y + (size_t)(gm + r) * N + gn)     = v0;
            *(float2*)(Y + (size_t)(gm + r + 8) * N + gn) = v1;
        }
    }
}

// ---------------- weight fp32 -> bf16 hi/lo ---------------------------------
__global__ void k_cvt(const float* __restrict__ x, __nv_bfloat16* __restrict__ h,
                      __nv_bfloat16* __restrict__ l, int n) {
    int i = (blockIdx.x * 256 + threadIdx.x) * 4;
    if (i >= n) return;
    float4 v = *(const float4*)(x + i);
    __nv_bfloat16 hh, ll;
    split_bf16(v.x, hh, ll); h[i+0] = hh; l[i+0] = ll;
    split_bf16(v.y, hh, ll); h[i+1] = hh; l[i+1] = ll;
    split_bf16(v.z, hh, ll); h[i+2] = hh; l[i+2] = ll;
    split_bf16(v.w, hh, ll); h[i+3] = hh; l[i+3] = ll;
}

// ---------------- transpose (B,C,L) -> (B,L,C), fp32 + bf16 hi/lo ----------
__global__ void k_transpose_in(const float* __restrict__ X, float* __restrict__ Y,
                               __nv_bfloat16* __restrict__ YH, __nv_bfloat16* __restrict__ YL) {
    __shared__ float tile[32][33];
    int b  = blockIdx.z;
    int l0 = blockIdx.x << 5, c0 = blockIdx.y << 5;
    int tx = threadIdx.x, ty = threadIdx.y;
    const float* Xb = X + (size_t)b*CC*LL;
    #pragma unroll
    for (int i = ty; i < 32; i += 8)
        tile[i][tx] = Xb[(size_t)(c0+i)*LL + l0 + tx];
    __syncthreads();
    size_t base = (size_t)b*LL*CC;
    #pragma unroll
    for (int i = ty; i < 32; i += 8) {
        float v = tile[tx][i];
        size_t o = base + (size_t)(l0+i)*CC + c0 + tx;
        Y[o] = v;
        __nv_bfloat16 hh, ll; split_bf16(v, hh, ll);
        YH[o] = hh; YL[o] = ll;
    }
}

// ---------------- out = transpose(H + A), (B,L,C) -> (B,C,L) ---------------
__global__ void k_add_transpose_out(const float* __restrict__ Hh, const float* __restrict__ A,
                                    float* __restrict__ OUT) {
    __shared__ float tile[32][33];
    int b  = blockIdx.z;
    int l0 = blockIdx.x << 5, c0 = blockIdx.y << 5;
    int tx = threadIdx.x, ty = threadIdx.y;
    const float* Hb = Hh + (size_t)b*LL*CC;
    const float* Ab = A  + (size_t)b*LL*CC;
    #pragma unroll
    for (int i = ty; i < 32; i += 8) {
        size_t o = (size_t)(l0+i)*CC + c0 + tx;
        tile[i][tx] = Hb[o] + Ab[o];
    }
    __syncthreads();
    float* Ob = OUT + (size_t)b*CC*LL;
    #pragma unroll
    for (int i = ty; i < 32; i += 8)
        Ob[(size_t)(c0+i)*LL + l0 + tx] = tile[tx][i];
}

// ---------------- row LayerNorm with fused epilogues + bf16 split out -------
// mode 0: plain LN ; 1: LN + per-64-chunk l2n (Wd==512) ; 2: LN*gamma + resid
// mode 3: LN + relu.
__global__ void k_ln(const float* __restrict__ in, int ld_in,
                     float* __restrict__ out,
                     const float* __restrict__ gam, const float* __restrict__ bet,
                     int Wd, int mode, const float* __restrict__ gamma_p,
                     const float* __restrict__ resid,
                     __nv_bfloat16* __restrict__ oh, __nv_bfloat16* __restrict__ ol) {
    int row = blockIdx.x;
    int tid = threadIdx.x;
    int E = Wd >> 8;                      // 2 or 8
    const float* xr = in + (size_t)row*ld_in + (size_t)tid*E;
    float v[8];
    float s = 0.f, s2 = 0.f;
    for (int i = 0; i < E; i++) { v[i] = xr[i]; s += v[i]; s2 += v[i]*v[i]; }

    __shared__ float rs[256], rs2[256];
    rs[tid] = s; rs2[tid] = s2;
    __syncthreads();
    for (int off = 128; off > 0; off >>= 1) {
        if (tid < off) { rs[tid] += rs[tid+off]; rs2[tid] += rs2[tid+off]; }
        __syncthreads();
    }
    float mu  = rs[0] / (float)Wd;
    float var = rs2[0] / (float)Wd - mu*mu;
    float rstd = rsqrtf(var + 1e-5f);

    float y[8];
    for (int i = 0; i < E; i++) {
        int c = tid*E + i;
        y[i] = (v[i] - mu)*rstd*gam[c] + bet[c];
    }
    if (mode == 1) {
        float qq = y[0]*y[0] + y[1]*y[1];
        #pragma unroll
        for (int o = 16; o > 0; o >>= 1) qq += __shfl_xor_sync(0xffffffffu, qq, o);
        float sc = 1.0f / fmaxf(sqrtf(qq), 1e-12f);
        y[0] *= sc; y[1] *= sc;
    } else if (mode == 2) {
        float gsc = gamma_p[0];
        const float* rr = resid + (size_t)row*Wd + (size_t)tid*E;
        for (int i = 0; i < E; i++) y[i] = y[i]*gsc + rr[i];
    } else if (mode == 3) {
        for (int i = 0; i < E; i++) y[i] = fmaxf(y[i], 0.f);
    }
    size_t obase = (size_t)row*Wd + (size_t)tid*E;
    if (out) {
        float* yr = out + obase;
        for (int i = 0; i < E; i++) yr[i] = y[i];
    }
    if (oh) {
        for (int i = 0; i < E; i++) {
            __nv_bfloat16 hh, ll; split_bf16(y[i], hh, ll);
            oh[obase + i] = hh; ol[obase + i] = ll;
        }
    }
}

// ---------------- q_probe = sum over L of QN --------------------------------
__global__ void k_probe_partial(const float* __restrict__ QN, float* __restrict__ part) {
    int b = blockIdx.x, ch = blockIdx.y;
    int c = threadIdx.x;
    const int CHUNK = LL / 32;
    const float* p = QN + ((size_t)b*LL + (size_t)ch*CHUNK)*CC + c;
    float s = 0.f;
    for (int i = 0; i < CHUNK; i++) s += p[(size_t)i*CC];
    part[((size_t)b*32 + ch)*CC + c] = s;
}
__global__ void k_probe_reduce(const float* __restrict__ part, float* __restrict__ probe) {
    int b = blockIdx.x; int c = threadIdx.x;
    float s = 0.f;
    for (int ch = 0; ch < 32; ch++) s += part[((size_t)b*32 + ch)*CC + c];
    probe[b*CC + c] = s;
}

// ---------------- score[b,h,l] = probe . (|k|+k) -----------------------------
__global__ void k_score(const float* __restrict__ KN, const float* __restrict__ probe,
                        float* __restrict__ score) {
    int gw   = (blockIdx.x * blockDim.x + threadIdx.x) >> 5;
    int lane = threadIdx.x & 31;
    if (gw >= BB*LL) return;
    int b = gw >> 12;
    int l = gw & (LL-1);
    const float* krow = KN + (size_t)gw*CC;
    const float* pr   = probe + b*CC;
    int c0 = lane << 4;
    float s = 0.f;
    #pragma unroll
    for (int j = 0; j < 16; j += 4) {
        float4 k4 = *(const float4*)(krow + c0 + j);
        float4 p4 = *(const float4*)(pr   + c0 + j);
        s += p4.x*(fabsf(k4.x)+k4.x) + p4.y*(fabsf(k4.y)+k4.y)
           + p4.z*(fabsf(k4.z)+k4.z) + p4.w*(fabsf(k4.w)+k4.w);
    }
    s += __shfl_xor_sync(0xffffffffu, s, 1);
    s += __shfl_xor_sync(0xffffffffu, s, 2);
    if ((lane & 3) == 0) {
        int h = lane >> 2;
        score[((size_t)(b*HH + h))*LL + l] = s;
    }
}

// ---------------- exact top-k via in-smem bitonic sort -----------------------
__global__ void k_topk(const float* __restrict__ score, int* __restrict__ idx) {
    __shared__ unsigned long long keys[LL];
    int bh = blockIdx.x;
    const float* s = score + (size_t)bh*LL;
    for (int i = threadIdx.x; i < LL; i += blockDim.x) {
        unsigned u = __float_as_uint(s[i]);
        u = (u & 0x80000000u) ? ~u : (u | 0x80000000u);
        keys[i] = ((unsigned long long)u << 32) | (unsigned)(LL-1-i);
    }
    __syncthreads();
    for (int k = 2; k <= LL; k <<= 1) {
        for (int j = k >> 1; j > 0; j >>= 1) {
            for (int i = threadIdx.x; i < LL; i += blockDim.x) {
                int ixj = i ^ j;
                if (ixj > i) {
                    unsigned long long a = keys[i], c = keys[ixj];
                    bool desc = (i & k) == 0;
                    if (desc ? (a < c) : (a > c)) { keys[i] = c; keys[ixj] = a; }
                }
            }
            __syncthreads();
        }
    }
    for (int t = threadIdx.x; t < TK; t += blockDim.x)
        idx[bh*TK + t] = (LL-1) - (int)(unsigned)(keys[t] & 0xffffffffu);
}

// ---------------- gather selected K/V rows per head -> bf16 hi/lo ------------
__global__ void k_gather(const float* __restrict__ KN, const float* __restrict__ VT,
                         const int* __restrict__ idx,
                         __nv_bfloat16* __restrict__ KCH, __nv_bfloat16* __restrict__ KCL,
                         __nv_bfloat16* __restrict__ VCH, __nv_bfloat16* __restrict__ VCL) {
    int bt = blockIdx.x;
    int b = bt / TK, t = bt % TK;
    int c = threadIdx.x;
    int h = c >> 6;
    int l = idx[(b*HH + h)*TK + t];
    size_t src = ((size_t)b*LL + l)*CC + c;
    size_t dst = (size_t)bt*CC + c;
    __nv_bfloat16 hh, ll;
    split_bf16(KN[src], hh, ll); KCH[dst] = hh; KCL[dst] = ll;
    split_bf16(VT[src], hh, ll); VCH[dst] = hh; VCL[dst] = ll;
}

// ---------------- attention: per (b,h,64-query tile), online softmax ---------
__global__ void k_attn(const float* __restrict__ QP, const float* __restrict__ KP,
                       const float* __restrict__ VP, const float* __restrict__ bk,
                       const float* __restrict__ bv,
                       __nv_bfloat16* __restrict__ AOH, __nv_bfloat16* __restrict__ AOL) {
    __shared__ float Ks[64][64];
    __shared__ float Vs[64][64];
    int bh = blockIdx.y;
    int b = bh >> 3, h = bh & 7;
    int l0 = blockIdx.x << 6;
    int tid = threadIdx.x;
    int g = tid >> 2;
    int r = tid & 3;
    int l = l0 + g;
    const int cbase = h*CHD + r*16;

    float q[16];
    const float* qrow = QP + ((size_t)b*LL + l)*CC + cbase;
    #pragma unroll
    for (int i = 0; i < 16; i++) q[i] = qrow[i];

    float acc[16];
    #pragma unroll
    for (int i = 0; i < 16; i++) acc[i] = 0.f;
    float m = -1e30f, denom = 0.f;

    for (int kc0 = 0; kc0 < TK; kc0 += 64) {
        for (int i = tid; i < 64*64; i += 256) {
            int rowk = i >> 6, cc = i & 63;
            size_t src = ((size_t)b*TK + kc0 + rowk)*CC + h*CHD + cc;
            Ks[rowk][cc] = KP[src];
            Vs[rowk][cc] = VP[src];
        }
        __syncthreads();
        for (int j = 0; j < 64; j++) {
            float part = 0.f;
            #pragma unroll
            for (int i = 0; i < 16; i++) part += q[i]*Ks[j][r*16 + i];
            part += __shfl_xor_sync(0xffffffffu, part, 1);
            part += __shfl_xor_sync(0xffffffffu, part, 2);
            float sc = part * 0.125f;
            if (sc > m) {
                float corr = __expf(m - sc);
                denom *= corr;
                #pragma unroll
                for (int i = 0; i < 16; i++) acc[i] *= corr;
                m = sc;
            }
            float p = __expf(sc - m);
            denom += p;
            #pragma unroll
            for (int i = 0; i < 16; i++) acc[i] += p*Vs[j][r*16 + i];
        }
        __syncthreads();
    }
    {
        float part = 0.f;
        #pragma unroll
        for (int i = 0; i < 16; i++) part += q[i]*bk[cbase + i];
        part += __shfl_xor_sync(0xffffffffu, part, 1);
        part += __shfl_xor_sync(0xffffffffu, part, 2);
        float sc = part * 0.125f;
        if (sc > m) {
            float corr = __expf(m - sc);
            denom *= corr;
            #pragma unroll
            for (int i = 0; i < 16; i++) acc[i] *= corr;
            m = sc;
        }
        float p = __expf(sc - m);
        denom += p;
        #pragma unroll
        for (int i = 0; i < 16; i++) acc[i] += p*bv[cbase + i];
    }
    float inv = 1.f / denom;
    size_t obase = ((size_t)b*LL + l)*CC + cbase;
    #pragma unroll
    for (int i = 0; i < 16; i++) {
        __nv_bfloat16 hh, ll; split_bf16(acc[i]*inv, hh, ll);
        AOH[obase + i] = hh; AOL[obase + i] = ll;
    }
}

// ---------------------------- launcher ---------------------------------------
extern "C" void kernel_launch(void* const* d_in, const int* in_sizes, int n_in,
                              void* d_out, int out_size) {
    const float* x         = (const float*)d_in[0];
    const float* q_conv_w  = (const float*)d_in[1];
    const float* q_conv_b  = (const float*)d_in[2];
    const float* q_ln_g    = (const float*)d_in[3];
    const float* q_ln_b    = (const float*)d_in[4];
    const float* kv_conv_w = (const float*)d_in[5];
    const float* kv_conv_b = (const float*)d_in[6];
    const float* k_ln_g    = (const float*)d_in[7];
    const float* k_ln_b    = (const float*)d_in[8];
    const float* v_ln_g    = (const float*)d_in[9];
    const float* v_ln_b    = (const float*)d_in[10];
    const float* in_proj_w = (const float*)d_in[11];
    const float* in_proj_b = (const float*)d_in[12];
    const float* bias_k    = (const float*)d_in[13];
    const float* bias_v    = (const float*)d_in[14];
    const float* out_proj_w= (const float*)d_in[15];
    const float* out_proj_b= (const float*)d_in[16];
    const float* attn_ln_g = (const float*)d_in[17];
    const float* attn_ln_b = (const float*)d_in[18];
    const float* gamma     = (const float*)d_in[19];
    const float* w1        = (const float*)d_in[20];
    const float* b1        = (const float*)d_in[21];
    const float* n1_g      = (const float*)d_in[22];
    const float* n1_b      = (const float*)d_in[23];
    const float* w2        = (const float*)d_in[24];
    const float* b2        = (const float*)d_in[25];
    const float* n2_g      = (const float*)d_in[26];
    const float* n2_b      = (const float*)d_in[27];
    float* out = (float*)d_out;

    float *xt, *q, *kv, *kn, *vt, *pp, *probe, *score, *kp, *vp, *qp, *a, *h1, *h2;
    int* idx;
    __nv_bfloat16 *xth,*xtl,*qh,*ql,*kch,*kcl,*vch,*vcl,*aoh,*aol,*ah,*al,*h1h,*h1l;
    __nv_bfloat16 *wqh,*wql,*wkvh,*wkvl,*winh,*winl,*woh,*wol,*w1h,*w1l,*w2h,*w2l;

    cudaGetSymbolAddress((void**)&xt,   g_xt);
    cudaGetSymbolAddress((void**)&q,    g_q);
    cudaGetSymbolAddress((void**)&kv,   g_kv);
    cudaGetSymbolAddress((void**)&kn,   g_kn);
    cudaGetSymbolAddress((void**)&vt,   g_vt);
    cudaGetSymbolAddress((void**)&pp,   g_pp);
    cudaGetSymbolAddress((void**)&probe,g_probe);
    cudaGetSymbolAddress((void**)&score,g_score);
    cudaGetSymbolAddress((void**)&idx,  g_idx);
    cudaGetSymbolAddress((void**)&kp,   g_kp);
    cudaGetSymbolAddress((void**)&vp,   g_vp);
    cudaGetSymbolAddress((void**)&qp,   g_qp);
    cudaGetSymbolAddress((void**)&a,    g_a);
    cudaGetSymbolAddress((void**)&h1,   g_h1);
    cudaGetSymbolAddress((void**)&h2,   g_h2);
    cudaGetSymbolAddress((void**)&xth,  g_xt_h); cudaGetSymbolAddress((void**)&xtl, g_xt_l);
    cudaGetSymbolAddress((void**)&qh,   g_q_h);  cudaGetSymbolAddress((void**)&ql,  g_q_l);
    cudaGetSymbolAddress((void**)&kch,  g_kc_h); cudaGetSymbolAddress((void**)&kcl, g_kc_l);
    cudaGetSymbolAddress((void**)&vch,  g_vc_h); cudaGetSymbolAddress((void**)&vcl, g_vc_l);
    cudaGetSymbolAddress((void**)&aoh,  g_ao_h); cudaGetSymbolAddress((void**)&aol, g_ao_l);
    cudaGetSymbolAddress((void**)&ah,   g_a_h);  cudaGetSymbolAddress((void**)&al,  g_a_l);
    cudaGetSymbolAddress((void**)&h1h,  g_h1_h); cudaGetSymbolAddress((void**)&h1l, g_h1_l);
    cudaGetSymbolAddress((void**)&wqh,  g_wq_h); cudaGetSymbolAddress((void**)&wql, g_wq_l);
    cudaGetSymbolAddress((void**)&wkvh, g_wkv_h);cudaGetSymbolAddress((void**)&wkvl,g_wkv_l);
    cudaGetSymbolAddress((void**)&winh, g_win_h);cudaGetSymbolAddress((void**)&winl,g_win_l);
    cudaGetSymbolAddress((void**)&woh,  g_wo_h); cudaGetSymbolAddress((void**)&wol, g_wo_l);
    cudaGetSymbolAddress((void**)&w1h,  g_w1_h); cudaGetSymbolAddress((void**)&w1l, g_w1_l);
    cudaGetSymbolAddress((void**)&w2h,  g_w2_h); cudaGetSymbolAddress((void**)&w2l, g_w2_l);

    cudaFuncSetAttribute(k_gemm_mma, cudaFuncAttributeMaxDynamicSharedMemorySize, 2*STAGE_BYTES);
    const int GS = 2*STAGE_BYTES;   // 81920

    // weight conversions
    k_cvt<<<(CC*CC)/1024,   256>>>(q_conv_w,  wqh,  wql,  CC*CC);
    k_cvt<<<(2*CC*CC)/1024, 256>>>(kv_conv_w, wkvh, wkvl, 2*CC*CC);
    k_cvt<<<(3*CC*CC)/1024, 256>>>(in_proj_w, winh, winl, 3*CC*CC);
    k_cvt<<<(CC*CC)/1024,   256>>>(out_proj_w,woh,  wol,  CC*CC);
    k_cvt<<<(MM*CC)/1024,   256>>>(w1,        w1h,  w1l,  MM*CC);
    k_cvt<<<(CC*MM)/1024,   256>>>(w2,        w2h,  w2l,  CC*MM);

    dim3 tgrid(LL/32, CC/32, BB), tblk(32, 8);
    k_transpose_in<<<tgrid, tblk>>>(x, xt, xth, xtl);

    // Q / KV projections
    k_gemm_mma<<<dim3(CC/128,   BLROWS/128), 256, GS>>>(xth, xtl, wqh,  wql,  q_conv_b,  q,  CC,   CC);
    k_gemm_mma<<<dim3(2*CC/128, BLROWS/128), 256, GS>>>(xth, xtl, wkvh, wkvl, kv_conv_b, kv, 2*CC, CC);

    // LayerNorms (+l2n for Q,K)
    k_ln<<<BLROWS, 256>>>(q,       CC,   q,  q_ln_g, q_ln_b, CC, 1, nullptr, nullptr, qh, ql);
    k_ln<<<BLROWS, 256>>>(kv,      2*CC, kn, k_ln_g, k_ln_b, CC, 1, nullptr, nullptr, nullptr, nullptr);
    k_ln<<<BLROWS, 256>>>(kv + CC, 2*CC, vt, v_ln_g, v_ln_b, CC, 0, nullptr, nullptr, nullptr, nullptr);

    // probe, score, top-k, gather
    k_probe_partial<<<dim3(BB, 32), CC>>>(q, pp);
    k_probe_reduce<<<BB, CC>>>(pp, probe);
    k_score<<<(BB*LL*32)/256, 256>>>(kn, probe, score);
    k_topk<<<BB*HH, 512>>>(score, idx);
    k_gather<<<BB*TK, CC>>>(kn, vt, idx, kch, kcl, vch, vcl);

    // in_proj
    k_gemm_mma<<<dim3(CC/128, BLROWS/128),  256, GS>>>(qh,  ql,  winh,           winl,           in_proj_b,        qp, CC, CC);
    k_gemm_mma<<<dim3(CC/128, (BB*TK)/128), 256, GS>>>(kch, kcl, winh + CC*CC,   winl + CC*CC,   in_proj_b + CC,   kp, CC, CC);
    k_gemm_mma<<<dim3(CC/128, (BB*TK)/128), 256, GS>>>(vch, vcl, winh + 2*CC*CC, winl + 2*CC*CC, in_proj_b + 2*CC, vp, CC, CC);

    // attention (257 keys: 256 selected + bias key) -> bf16 hi/lo
    k_attn<<<dim3(LL/64, BB*HH), 256>>>(qp, kp, vp, bias_k, bias_v, aoh, aol);

    // out_proj -> h2(temp), attn LN * gamma + x residual -> a (+ hi/lo)
    k_gemm_mma<<<dim3(CC/128, BLROWS/128), 256, GS>>>(aoh, aol, woh, wol, out_proj_b, h2, CC, CC);
    k_ln<<<BLROWS, 256>>>(h2, CC, a, attn_ln_g, attn_ln_b, CC, 2, gamma, xt, ah, al);

    // FFN
    k_gemm_mma<<<dim3(MM/128, BLROWS/128), 256, GS>>>(ah, al, w1h, w1l, b1, h1, MM, CC);
    k_ln<<<BLROWS, 256>>>(h1, MM, nullptr, n1_g, n1_b, MM, 3, nullptr, nullptr, h1h, h1l);
    k_gemm_mma<<<dim3(CC/128, BLROWS/128), 256, GS>>>(h1h, h1l, w2h, w2l, b2, h2, CC, MM);
    k_ln<<<BLROWS, 256>>>(h2, CC, h2, n2_g, n2_b, CC, 3, nullptr, nullptr, nullptr, nullptr);

    // out = transpose(h2 + a)
    k_add_transpose_out<<<tgrid, tblk>>>(h2, a, out);
}

// round 5
// speedup vs baseline: 1.7470x; 1.0410x over previous
#include <cuda_runtime.h>
#include <cuda_bf16.h>
#include <math.h>
#include <stdint.h>

// Problem constants
#define BB   8
#define CC   512
#define LL   4096
#define HH   8
#define TK   256
#define MM   2048
#define CHD  64
#define BLROWS (BB*LL)   // 32768

// ---------------- scratch (device globals; no allocation allowed) ----------
__device__ __align__(16) float g_xt  [(size_t)BB*LL*CC];
__device__ __align__(16) float g_q   [(size_t)BB*LL*CC];
__device__ __align__(16) float g_kv  [(size_t)BB*LL*2*CC];
__device__ __align__(16) float g_kn  [(size_t)BB*LL*CC];
__device__ __align__(16) float g_vt  [(size_t)BB*LL*CC];
__device__ __align__(16) float g_pp  [(size_t)BB*32*CC];
__device__ __align__(16) float g_probe[BB*CC];
__device__ __align__(16) float g_score[BB*HH*LL];
__device__ __align__(16) int   g_idx [BB*HH*TK];
__device__ __align__(16) float g_kp  [(size_t)BB*TK*CC];
__device__ __align__(16) float g_vp  [(size_t)BB*TK*CC];
__device__ __align__(16) float g_qp  [(size_t)BB*LL*CC];
__device__ __align__(16) float g_a   [(size_t)BB*LL*CC];
__device__ __align__(16) float g_h2  [(size_t)BB*LL*CC];

// bf16 hi/lo split activations
__device__ __align__(16) __nv_bfloat16 g_xt_h[(size_t)BB*LL*CC];
__device__ __align__(16) __nv_bfloat16 g_xt_l[(size_t)BB*LL*CC];
__device__ __align__(16) __nv_bfloat16 g_q_h [(size_t)BB*LL*CC];
__device__ __align__(16) __nv_bfloat16 g_q_l [(size_t)BB*LL*CC];
__device__ __align__(16) __nv_bfloat16 g_kc_h[(size_t)BB*TK*CC];
__device__ __align__(16) __nv_bfloat16 g_kc_l[(size_t)BB*TK*CC];
__device__ __align__(16) __nv_bfloat16 g_vc_h[(size_t)BB*TK*CC];
__device__ __align__(16) __nv_bfloat16 g_vc_l[(size_t)BB*TK*CC];
__device__ __align__(16) __nv_bfloat16 g_ao_h[(size_t)BB*LL*CC];
__device__ __align__(16) __nv_bfloat16 g_ao_l[(size_t)BB*LL*CC];
__device__ __align__(16) __nv_bfloat16 g_a_h [(size_t)BB*LL*CC];
__device__ __align__(16) __nv_bfloat16 g_a_l [(size_t)BB*LL*CC];
__device__ __align__(16) __nv_bfloat16 g_h1_h[(size_t)BB*LL*MM];
__device__ __align__(16) __nv_bfloat16 g_h1_l[(size_t)BB*LL*MM];
__device__ __align__(16) float g_h1  [(size_t)BB*LL*MM];

// bf16 hi/lo weights
__device__ __align__(16) __nv_bfloat16 g_wq_h [CC*CC],    g_wq_l [CC*CC];
__device__ __align__(16) __nv_bfloat16 g_wkv_h[2*CC*CC],  g_wkv_l[2*CC*CC];
__device__ __align__(16) __nv_bfloat16 g_win_h[3*CC*CC],  g_win_l[3*CC*CC];
__device__ __align__(16) __nv_bfloat16 g_wo_h [CC*CC],    g_wo_l [CC*CC];
__device__ __align__(16) __nv_bfloat16 g_w1_h [MM*CC],    g_w1_l [MM*CC];
__device__ __align__(16) __nv_bfloat16 g_w2_h [CC*MM],    g_w2_l [CC*MM];

// ================= helpers ===================================================
static __device__ __forceinline__ uint32_t smem_u32(const void* p) {
    uint32_t a;
    asm("{ .reg .u64 t; cvta.to.shared.u64 t, %1; cvt.u32.u64 %0, t; }"
        : "=r"(a) : "l"(p));
    return a;
}
static __device__ __forceinline__ void split_bf16(float v, __nv_bfloat16& h, __nv_bfloat16& l) {
    h = __float2bfloat16(v);
    l = __float2bfloat16(v - __bfloat162float(h));
}
static __device__ __forceinline__ void ldmA(uint32_t* r, uint32_t addr) {
    asm volatile("ldmatrix.sync.aligned.m8n8.x4.shared.b16 {%0,%1,%2,%3}, [%4];"
                 : "=r"(r[0]), "=r"(r[1]), "=r"(r[2]), "=r"(r[3]) : "r"(addr));
}
static __device__ __forceinline__ void ldmB(uint32_t* r, uint32_t addr) {
    asm volatile("ldmatrix.sync.aligned.m8n8.x2.shared.b16 {%0,%1}, [%2];"
                 : "=r"(r[0]), "=r"(r[1]) : "r"(addr));
}
static __device__ __forceinline__ void mma16816(float* d, const uint32_t* a, const uint32_t* b) {
    asm volatile(
        "mma.sync.aligned.m16n8k16.row.col.f32.bf16.bf16.f32 "
        "{%0,%1,%2,%3}, {%4,%5,%6,%7}, {%8,%9}, {%0,%1,%2,%3};"
        : "+f"(d[0]), "+f"(d[1]), "+f"(d[2]), "+f"(d[3])
        : "r"(a[0]), "r"(a[1]), "r"(a[2]), "r"(a[3]), "r"(b[0]), "r"(b[1]));
}
static __device__ __forceinline__ void cpasync16(uint32_t saddr, const void* gaddr) {
    asm volatile("cp.async.cg.shared.global [%0], [%1], 16;"
                 :: "r"(saddr), "l"(gaddr) : "memory");
}

// ================= tensor-core GEMM via mma.sync ============================
// Y(row,col) = sum_K Xhi/lo(row,K) * Whi/lo(col,K) + bias[col]
// CTA tile 128x256, BK=32, 8 warps (2M x 4N), warp tile 64x64 (4mf x 8nt).
// bf16 3-product split: D += Ah*Bh + Ah*Bl + Al*Bh.
// smem per stage: Ah(128x80) Al(128x80) Bh(256x80) Bl(256x80) = 61440B; 3 stages.
#define AH_OFF 0
#define AL_OFF 10240
#define BH_OFF 20480
#define BL_OFF 40960
#define STG    61440
__global__ void __launch_bounds__(256, 1) k_gemm_mma(
    const __nv_bfloat16* __restrict__ Ah, const __nv_bfloat16* __restrict__ Al,
    const __nv_bfloat16* __restrict__ Bh, const __nv_bfloat16* __restrict__ Bl,
    const float* __restrict__ bias, float* __restrict__ Y, int N, int K)
{
    extern __shared__ __align__(128) char smem[];
    const uint32_t sb = smem_u32(smem);
    const int tid  = threadIdx.x;
    const int wid  = tid >> 5, lane = tid & 31;
    const int wm   = wid & 1;              // warp M 0..1 (64 rows)
    const int wn   = wid >> 1;             // warp N 0..3 (64 cols)
    const int bm = blockIdx.y << 7, bn = blockIdx.x << 8;

    const int nch = K >> 5;                // chunks of BK=32

    float acc[4][8][4];
    #pragma unroll
    for (int m = 0; m < 4; m++)
        #pragma unroll
        for (int n = 0; n < 8; n++)
            #pragma unroll
            for (int v = 0; v < 4; v++) acc[m][n][v] = 0.f;

    // ---- async load of one chunk into stage s ----
    auto load_chunk = [&](int ck, int s) {
        const int k0 = ck << 5;
        const uint32_t so = sb + s * STG;
        #pragma unroll
        for (int i = 0; i < 12; i++) {
            const int idx = tid + (i << 8);   // 0..3071 16B units
            const __nv_bfloat16* src;
            int local; uint32_t dst; int rb;
            if (i < 2)      { src = Ah; local = idx;        dst = AH_OFF; rb = bm; }
            else if (i < 4) { src = Al; local = idx - 512;  dst = AL_OFF; rb = bm; }
            else if (i < 8) { src = Bh; local = idx - 1024; dst = BH_OFF; rb = bn; }
            else            { src = Bl; local = idx - 2048; dst = BL_OFF; rb = bn; }
            const int row = local >> 2, seg = local & 3;
            cpasync16(so + dst + row * 80 + (seg << 4),
                      src + (size_t)(rb + row) * K + k0 + (seg << 3));
        }
        asm volatile("cp.async.commit_group;" ::: "memory");
    };

    load_chunk(0, 0);
    load_chunk(1, 1);

    // ldmatrix lane offsets
    const uint32_t aRow = (lane & 7) + ((lane >> 3) & 1) * 8;
    const uint32_t aKof = (lane >> 4) * 8;
    const uint32_t bRow = (lane & 7);
    const uint32_t bKof = ((lane >> 3) & 1) * 8;

    for (int ck = 0; ck < nch; ck++) {
        if (ck + 2 < nch) {
            load_chunk(ck + 2, (ck + 2) % 3);
            asm volatile("cp.async.wait_group 2;" ::: "memory");
        } else if (ck + 1 < nch) {
            asm volatile("cp.async.wait_group 1;" ::: "memory");
        } else {
            asm volatile("cp.async.wait_group 0;" ::: "memory");
        }
        __syncthreads();

        const uint32_t so = sb + (ck % 3) * STG;
        #pragma unroll
        for (int ks = 0; ks < 2; ks++) {
            uint32_t ah[4][4], al[4][4];
            #pragma unroll
            for (int mf = 0; mf < 4; mf++) {
                uint32_t row = wm * 64 + mf * 16 + aRow;
                uint32_t off = row * 80 + (aKof + ks * 16) * 2;
                ldmA(ah[mf], so + AH_OFF + off);
                ldmA(al[mf], so + AL_OFF + off);
            }
            #pragma unroll
            for (int nt = 0; nt < 8; nt++) {
                uint32_t row = wn * 64 + nt * 8 + bRow;
                uint32_t off = row * 80 + (bKof + ks * 16) * 2;
                uint32_t bh[2], bl[2];
                ldmB(bh, so + BH_OFF + off);
                ldmB(bl, so + BL_OFF + off);
                #pragma unroll
                for (int mf = 0; mf < 4; mf++) {
                    mma16816(acc[mf][nt], ah[mf], bh);
                    mma16816(acc[mf][nt], ah[mf], bl);
                    mma16816(acc[mf][nt], al[mf], bh);
                }
            }
        }
        __syncthreads();
    }

    // ---- epilogue: bias add, direct fp32 stores ----
    const int r  = lane >> 2;
    const int c2 = (lane & 3) << 1;
    #pragma unroll
    for (int mf = 0; mf < 4; mf++) {
        const int gm = bm + wm * 64 + mf * 16;
        #pragma unroll
        for (int nt = 0; nt < 8; nt++) {
            const int gn = bn + wn * 64 + nt * 8 + c2;
            float bx = bias[gn], by = bias[gn + 1];
            float2 v0 = make_float2(acc[mf][nt][0] + bx, acc[mf][nt][1] + by);
            float2 v1 = make_float2(acc[mf][nt][2] + bx, acc[mf][nt][3] + by);
            *(float2*)(Y + (size_t)(gm + r) * N + gn)     = v0;
            *(float2*)(Y + (size_t)(gm + r + 8) * N + gn) = v1;
        }
    }
}

// ---------------- weight fp32 -> bf16 hi/lo ---------------------------------
__global__ void k_cvt(const float* __restrict__ x, __nv_bfloat16* __restrict__ h,
                      __nv_bfloat16* __restrict__ l, int n) {
    int i = (blockIdx.x * 256 + threadIdx.x) * 4;
    if (i >= n) return;
    float4 v = *(const float4*)(x + i);
    __nv_bfloat16 hh, ll;
    split_bf16(v.x, hh, ll); h[i+0] = hh; l[i+0] = ll;
    split_bf16(v.y, hh, ll); h[i+1] = hh; l[i+1] = ll;
    split_bf16(v.z, hh, ll); h[i+2] = hh; l[i+2] = ll;
    split_bf16(v.w, hh, ll); h[i+3] = hh; l[i+3] = ll;
}

// ---------------- transpose (B,C,L) -> (B,L,C), fp32 + bf16 hi/lo ----------
__global__ void k_transpose_in(const float* __restrict__ X, float* __restrict__ Y,
                               __nv_bfloat16* __restrict__ YH, __nv_bfloat16* __restrict__ YL) {
    __shared__ float tile[32][33];
    int b  = blockIdx.z;
    int l0 = blockIdx.x << 5, c0 = blockIdx.y << 5;
    int tx = threadIdx.x, ty = threadIdx.y;
    const float* Xb = X + (size_t)b*CC*LL;
    #pragma unroll
    for (int i = ty; i < 32; i += 8)
        tile[i][tx] = Xb[(size_t)(c0+i)*LL + l0 + tx];
    __syncthreads();
    size_t base = (size_t)b*LL*CC;
    #pragma unroll
    for (int i = ty; i < 32; i += 8) {
        float v = tile[tx][i];
        size_t o = base + (size_t)(l0+i)*CC + c0 + tx;
        Y[o] = v;
        __nv_bfloat16 hh, ll; split_bf16(v, hh, ll);
        YH[o] = hh; YL[o] = ll;
    }
}

// ---------------- out = transpose(H + A), (B,L,C) -> (B,C,L) ---------------
__global__ void k_add_transpose_out(const float* __restrict__ Hh, const float* __restrict__ A,
                                    float* __restrict__ OUT) {
    __shared__ float tile[32][33];
    int b  = blockIdx.z;
    int l0 = blockIdx.x << 5, c0 = blockIdx.y << 5;
    int tx = threadIdx.x, ty = threadIdx.y;
    const float* Hb = Hh + (size_t)b*LL*CC;
    const float* Ab = A  + (size_t)b*LL*CC;
    #pragma unroll
    for (int i = ty; i < 32; i += 8) {
        size_t o = (size_t)(l0+i)*CC + c0 + tx;
        tile[i][tx] = Hb[o] + Ab[o];
    }
    __syncthreads();
    float* Ob = OUT + (size_t)b*CC*LL;
    #pragma unroll
    for (int i = ty; i < 32; i += 8)
        Ob[(size_t)(c0+i)*LL + l0 + tx] = tile[tx][i];
}

// ---------------- warp-per-row LayerNorm, Wd=512, fused epilogues -----------
// mode 0: plain LN ; 1: LN + per-64-chunk l2n ; 2: LN*gamma + resid ; 3: relu
__global__ void k_ln512(const float* __restrict__ in, int ld_in,
                        float* __restrict__ out,
                        const float* __restrict__ gam, const float* __restrict__ bet,
                        int mode, const float* __restrict__ gamma_p,
                        const float* __restrict__ resid,
                        __nv_bfloat16* __restrict__ oh, __nv_bfloat16* __restrict__ ol) {
    const int lane = threadIdx.x & 31;
    const int row  = blockIdx.x * 8 + (threadIdx.x >> 5);
    const float* xr = in + (size_t)row * ld_in + lane * 16;

    float v[16];
    float s = 0.f, s2 = 0.f;
    #pragma unroll
    for (int j = 0; j < 16; j += 4) {
        float4 t = *(const float4*)(xr + j);
        v[j]=t.x; v[j+1]=t.y; v[j+2]=t.z; v[j+3]=t.w;
        s += t.x+t.y+t.z+t.w;
        s2 += t.x*t.x+t.y*t.y+t.z*t.z+t.w*t.w;
    }
    #pragma unroll
    for (int o = 16; o > 0; o >>= 1) {
        s  += __shfl_xor_sync(0xffffffffu, s,  o);
        s2 += __shfl_xor_sync(0xffffffffu, s2, o);
    }
    const float mu = s * (1.f/512.f);
    const float rstd = rsqrtf(s2 * (1.f/512.f) - mu*mu + 1e-5f);

    float y[16];
    const int cb = lane * 16;
    #pragma unroll
    for (int i = 0; i < 16; i++)
        y[i] = (v[i] - mu) * rstd * gam[cb + i] + bet[cb + i];

    if (mode == 1) {           // l2n over 64-ch chunk = 4 adjacent lanes
        float qq = 0.f;
        #pragma unroll
        for (int i = 0; i < 16; i++) qq += y[i]*y[i];
        qq += __shfl_xor_sync(0xffffffffu, qq, 1);
        qq += __shfl_xor_sync(0xffffffffu, qq, 2);
        float sc = 1.f / fmaxf(sqrtf(qq), 1e-12f);
        #pragma unroll
        for (int i = 0; i < 16; i++) y[i] *= sc;
    } else if (mode == 2) {
        float gsc = gamma_p[0];
        const float* rr = resid + (size_t)row * 512 + cb;
        #pragma unroll
        for (int i = 0; i < 16; i++) y[i] = y[i]*gsc + rr[i];
    } else if (mode == 3) {
        #pragma unroll
        for (int i = 0; i < 16; i++) y[i] = fmaxf(y[i], 0.f);
    }
    size_t ob = (size_t)row * 512 + cb;
    if (out) {
        #pragma unroll
        for (int j = 0; j < 16; j += 4)
            *(float4*)(out + ob + j) = make_float4(y[j], y[j+1], y[j+2], y[j+3]);
    }
    if (oh) {
        #pragma unroll
        for (int i = 0; i < 16; i++) {
            __nv_bfloat16 hh, ll; split_bf16(y[i], hh, ll);
            oh[ob + i] = hh; ol[ob + i] = ll;
        }
    }
}

// ---------------- warp-per-row LN+relu, Wd=2048, bf16 hi/lo out only --------
__global__ void k_ln2048(const float* __restrict__ in,
                         const float* __restrict__ gam, const float* __restrict__ bet,
                         __nv_bfloat16* __restrict__ oh, __nv_bfloat16* __restrict__ ol) {
    const int lane = threadIdx.x & 31;
    const int row  = blockIdx.x * 8 + (threadIdx.x >> 5);
    const float* xr = in + (size_t)row * 2048;

    float s = 0.f, s2 = 0.f;
    #pragma unroll
    for (int w = 0; w < 16; w++) {
        float4 t = *(const float4*)(xr + ((w*32 + lane) << 2));
        s  += t.x+t.y+t.z+t.w;
        s2 += t.x*t.x+t.y*t.y+t.z*t.z+t.w*t.w;
    }
    #pragma unroll
    for (int o = 16; o > 0; o >>= 1) {
        s  += __shfl_xor_sync(0xffffffffu, s,  o);
        s2 += __shfl_xor_sync(0xffffffffu, s2, o);
    }
    const float mu = s * (1.f/2048.f);
    const float rstd = rsqrtf(s2 * (1.f/2048.f) - mu*mu + 1e-5f);

    #pragma unroll
    for (int w = 0; w < 16; w++) {
        const int e = (w*32 + lane) << 2;
        float4 t = *(const float4*)(xr + e);
        float4 g = *(const float4*)(gam + e);
        float4 bb = *(const float4*)(bet + e);
        float y0 = fmaxf((t.x-mu)*rstd*g.x + bb.x, 0.f);
        float y1 = fmaxf((t.y-mu)*rstd*g.y + bb.y, 0.f);
        float y2 = fmaxf((t.z-mu)*rstd*g.z + bb.z, 0.f);
        float y3 = fmaxf((t.w-mu)*rstd*g.w + bb.w, 0.f);
        size_t ob = (size_t)row * 2048 + e;
        __nv_bfloat16 hh, ll;
        split_bf16(y0, hh, ll); oh[ob+0]=hh; ol[ob+0]=ll;
        split_bf16(y1, hh, ll); oh[ob+1]=hh; ol[ob+1]=ll;
        split_bf16(y2, hh, ll); oh[ob+2]=hh; ol[ob+2]=ll;
        split_bf16(y3, hh, ll); oh[ob+3]=hh; ol[ob+3]=ll;
    }
}

// ---------------- q_probe = sum over L of QN --------------------------------
__global__ void k_probe_partial(const float* __restrict__ QN, float* __restrict__ part) {
    int b = blockIdx.x, ch = blockIdx.y;
    int c = threadIdx.x;
    const int CHUNK = LL / 32;
    const float* p = QN + ((size_t)b*LL + (size_t)ch*CHUNK)*CC + c;
    float s = 0.f;
    for (int i = 0; i < CHUNK; i++) s += p[(size_t)i*CC];
    part[((size_t)b*32 + ch)*CC + c] = s;
}
__global__ void k_probe_reduce(const float* __restrict__ part, float* __restrict__ probe) {
    int b = blockIdx.x; int c = threadIdx.x;
    float s = 0.f;
    for (int ch = 0; ch < 32; ch++) s += part[((size_t)b*32 + ch)*CC + c];
    probe[b*CC + c] = s;
}

// ---------------- score[b,h,l] = probe . (|k|+k) -----------------------------
__global__ void k_score(const float* __restrict__ KN, const float* __restrict__ probe,
                        float* __restrict__ score) {
    int gw   = (blockIdx.x * blockDim.x + threadIdx.x) >> 5;
    int lane = threadIdx.x & 31;
    if (gw >= BB*LL) return;
    int b = gw >> 12;
    int l = gw & (LL-1);
    const float* krow = KN + (size_t)gw*CC;
    const float* pr   = probe + b*CC;
    int c0 = lane << 4;
    float s = 0.f;
    #pragma unroll
    for (int j = 0; j < 16; j += 4) {
        float4 k4 = *(const float4*)(krow + c0 + j);
        float4 p4 = *(const float4*)(pr   + c0 + j);
        s += p4.x*(fabsf(k4.x)+k4.x) + p4.y*(fabsf(k4.y)+k4.y)
           + p4.z*(fabsf(k4.z)+k4.z) + p4.w*(fabsf(k4.w)+k4.w);
    }
    s += __shfl_xor_sync(0xffffffffu, s, 1);
    s += __shfl_xor_sync(0xffffffffu, s, 2);
    if ((lane & 3) == 0) {
        int h = lane >> 2;
        score[((size_t)(b*HH + h))*LL + l] = s;
    }
}

// ---------------- exact top-k via in-smem bitonic sort -----------------------
__global__ void k_topk(const float* __restrict__ score, int* __restrict__ idx) {
    __shared__ unsigned long long keys[LL];
    int bh = blockIdx.x;
    const float* s = score + (size_t)bh*LL;
    for (int i = threadIdx.x; i < LL; i += blockDim.x) {
        unsigned u = __float_as_uint(s[i]);
        u = (u & 0x80000000u) ? ~u : (u | 0x80000000u);
        keys[i] = ((unsigned long long)u << 32) | (unsigned)(LL-1-i);
    }
    __syncthreads();
    for (int k = 2; k <= LL; k <<= 1) {
        for (int j = k >> 1; j > 0; j >>= 1) {
            for (int i = threadIdx.x; i < LL; i += blockDim.x) {
                int ixj = i ^ j;
                if (ixj > i) {
                    unsigned long long a = keys[i], c = keys[ixj];
                    bool desc = (i & k) == 0;
                    if (desc ? (a < c) : (a > c)) { keys[i] = c; keys[ixj] = a; }
                }
            }
            __syncthreads();
        }
    }
    for (int t = threadIdx.x; t < TK; t += blockDim.x)
        idx[bh*TK + t] = (LL-1) - (int)(unsigned)(keys[t] & 0xffffffffu);
}

// ---------------- gather selected K/V rows per head -> bf16 hi/lo ------------
__global__ void k_gather(const float* __restrict__ KN, const float* __restrict__ VT,
                         const int* __restrict__ idx,
                         __nv_bfloat16* __restrict__ KCH, __nv_bfloat16* __restrict__ KCL,
                         __nv_bfloat16* __restrict__ VCH, __nv_bfloat16* __restrict__ VCL) {
    int bt = blockIdx.x;
    int b = bt / TK, t = bt % TK;
    int c = threadIdx.x;
    int h = c >> 6;
    int l = idx[(b*HH + h)*TK + t];
    size_t src = ((size_t)b*LL + l)*CC + c;
    size_t dst = (size_t)bt*CC + c;
    __nv_bfloat16 hh, ll;
    split_bf16(KN[src], hh, ll); KCH[dst] = hh; KCL[dst] = ll;
    split_bf16(VT[src], hh, ll); VCH[dst] = hh; VCL[dst] = ll;
}

// ---------------- attention: per (b,h,64-query tile), online softmax ---------
__global__ void k_attn(const float* __restrict__ QP, const float* __restrict__ KP,
                       const float* __restrict__ VP, const float* __restrict__ bk,
                       const float* __restrict__ bv,
                       __nv_bfloat16* __restrict__ AOH, __nv_bfloat16* __restrict__ AOL) {
    __shared__ float Ks[64][64];
    __shared__ float Vs[64][64];
    int bh = blockIdx.y;
    int b = bh >> 3, h = bh & 7;
    int l0 = blockIdx.x << 6;
    int tid = threadIdx.x;
    int g = tid >> 2;
    int r = tid & 3;
    int l = l0 + g;
    const int cbase = h*CHD + r*16;

    float q[16];
    const float* qrow = QP + ((size_t)b*LL + l)*CC + cbase;
    #pragma unroll
    for (int i = 0; i < 16; i++) q[i] = qrow[i];

    float acc[16];
    #pragma unroll
    for (int i = 0; i < 16; i++) acc[i] = 0.f;
    float m = -1e30f, denom = 0.f;

    for (int kc0 = 0; kc0 < TK; kc0 += 64) {
        for (int i = tid; i < 64*64; i += 256) {
            int rowk = i >> 6, cc = i & 63;
            size_t src = ((size_t)b*TK + kc0 + rowk)*CC + h*CHD + cc;
            Ks[rowk][cc] = KP[src];
            Vs[rowk][cc] = VP[src];
        }
        __syncthreads();
        for (int j = 0; j < 64; j++) {
            float part = 0.f;
            #pragma unroll
            for (int i = 0; i < 16; i++) part += q[i]*Ks[j][r*16 + i];
            part += __shfl_xor_sync(0xffffffffu, part, 1);
            part += __shfl_xor_sync(0xffffffffu, part, 2);
            float sc = part * 0.125f;
            if (sc > m) {
                float corr = __expf(m - sc);
                denom *= corr;
                #pragma unroll
                for (int i = 0; i < 16; i++) acc[i] *= corr;
                m = sc;
            }
            float p = __expf(sc - m);
            denom += p;
            #pragma unroll
            for (int i = 0; i < 16; i++) acc[i] += p*Vs[j][r*16 + i];
        }
        __syncthreads();
    }
    {
        float part = 0.f;
        #pragma unroll
        for (int i = 0; i < 16; i++) part += q[i]*bk[cbase + i];
        part += __shfl_xor_sync(0xffffffffu, part, 1);
        part += __shfl_xor_sync(0xffffffffu, part, 2);
        float sc = part * 0.125f;
        if (sc > m) {
            float corr = __expf(m - sc);
            denom *= corr;
            #pragma unroll
            for (int i = 0; i < 16; i++) acc[i] *= corr;
            m = sc;
        }
        float p = __expf(sc - m);
        denom += p;
        #pragma unroll
        for (int i = 0; i < 16; i++) acc[i] += p*bv[cbase + i];
    }
    float inv = 1.f / denom;
    size_t obase = ((size_t)b*LL + l)*CC + cbase;
    #pragma unroll
    for (int i = 0; i < 16; i++) {
        __nv_bfloat16 hh, ll; split_bf16(acc[i]*inv, hh, ll);
        AOH[obase + i] = hh; AOL[obase + i] = ll;
    }
}

// ---------------------------- launcher ---------------------------------------
extern "C" void kernel_launch(void* const* d_in, const int* in_sizes, int n_in,
                              void* d_out, int out_size) {
    const float* x         = (const float*)d_in[0];
    const float* q_conv_w  = (const float*)d_in[1];
    const float* q_conv_b  = (const float*)d_in[2];
    const float* q_ln_g    = (const float*)d_in[3];
    const float* q_ln_b    = (const float*)d_in[4];
    const float* kv_conv_w = (const float*)d_in[5];
    const float* kv_conv_b = (const float*)d_in[6];
    const float* k_ln_g    = (const float*)d_in[7];
    const float* k_ln_b    = (const float*)d_in[8];
    const float* v_ln_g    = (const float*)d_in[9];
    const float* v_ln_b    = (const float*)d_in[10];
    const float* in_proj_w = (const float*)d_in[11];
    const float* in_proj_b = (const float*)d_in[12];
    const float* bias_k    = (const float*)d_in[13];
    const float* bias_v    = (const float*)d_in[14];
    const float* out_proj_w= (const float*)d_in[15];
    const float* out_proj_b= (const float*)d_in[16];
    const float* attn_ln_g = (const float*)d_in[17];
    const float* attn_ln_b = (const float*)d_in[18];
    const float* gamma     = (const float*)d_in[19];
    const float* w1        = (const float*)d_in[20];
    const float* b1        = (const float*)d_in[21];
    const float* n1_g      = (const float*)d_in[22];
    const float* n1_b      = (const float*)d_in[23];
    const float* w2        = (const float*)d_in[24];
    const float* b2        = (const float*)d_in[25];
    const float* n2_g      = (const float*)d_in[26];
    const float* n2_b      = (const float*)d_in[27];
    float* out = (float*)d_out;

    float *xt, *q, *kv, *kn, *vt, *pp, *probe, *score, *kp, *vp, *qp, *a, *h1, *h2;
    int* idx;
    __nv_bfloat16 *xth,*xtl,*qh,*ql,*kch,*kcl,*vch,*vcl,*aoh,*aol,*ah,*al,*h1h,*h1l;
    __nv_bfloat16 *wqh,*wql,*wkvh,*wkvl,*winh,*winl,*woh,*wol,*w1h,*w1l,*w2h,*w2l;

    cudaGetSymbolAddress((void**)&xt,   g_xt);
    cudaGetSymbolAddress((void**)&q,    g_q);
    cudaGetSymbolAddress((void**)&kv,   g_kv);
    cudaGetSymbolAddress((void**)&kn,   g_kn);
    cudaGetSymbolAddress((void**)&vt,   g_vt);
    cudaGetSymbolAddress((void**)&pp,   g_pp);
    cudaGetSymbolAddress((void**)&probe,g_probe);
    cudaGetSymbolAddress((void**)&score,g_score);
    cudaGetSymbolAddress((void**)&idx,  g_idx);
    cudaGetSymbolAddress((void**)&kp,   g_kp);
    cudaGetSymbolAddress((void**)&vp,   g_vp);
    cudaGetSymbolAddress((void**)&qp,   g_qp);
    cudaGetSymbolAddress((void**)&a,    g_a);
    cudaGetSymbolAddress((void**)&h1,   g_h1);
    cudaGetSymbolAddress((void**)&h2,   g_h2);
    cudaGetSymbolAddress((void**)&xth,  g_xt_h); cudaGetSymbolAddress((void**)&xtl, g_xt_l);
    cudaGetSymbolAddress((void**)&qh,   g_q_h);  cudaGetSymbolAddress((void**)&ql,  g_q_l);
    cudaGetSymbolAddress((void**)&kch,  g_kc_h); cudaGetSymbolAddress((void**)&kcl, g_kc_l);
    cudaGetSymbolAddress((void**)&vch,  g_vc_h); cudaGetSymbolAddress((void**)&vcl, g_vc_l);
    cudaGetSymbolAddress((void**)&aoh,  g_ao_h); cudaGetSymbolAddress((void**)&aol, g_ao_l);
    cudaGetSymbolAddress((void**)&ah,   g_a_h);  cudaGetSymbolAddress((void**)&al,  g_a_l);
    cudaGetSymbolAddress((void**)&h1h,  g_h1_h); cudaGetSymbolAddress((void**)&h1l, g_h1_l);
    cudaGetSymbolAddress((void**)&wqh,  g_wq_h); cudaGetSymbolAddress((void**)&wql, g_wq_l);
    cudaGetSymbolAddress((void**)&wkvh, g_wkv_h);cudaGetSymbolAddress((void**)&wkvl,g_wkv_l);
    cudaGetSymbolAddress((void**)&winh, g_win_h);cudaGetSymbolAddress((void**)&winl,g_win_l);
    cudaGetSymbolAddress((void**)&woh,  g_wo_h); cudaGetSymbolAddress((void**)&wol, g_wo_l);
    cudaGetSymbolAddress((void**)&w1h,  g_w1_h); cudaGetSymbolAddress((void**)&w1l, g_w1_l);
    cudaGetSymbolAddress((void**)&w2h,  g_w2_h); cudaGetSymbolAddress((void**)&w2l, g_w2_l);

    cudaFuncSetAttribute(k_gemm_mma, cudaFuncAttributeMaxDynamicSharedMemorySize, 3*STG);
    const int GS = 3*STG;   // 184320

    // weight conversions
    k_cvt<<<(CC*CC)/1024,   256>>>(q_conv_w,  wqh,  wql,  CC*CC);
    k_cvt<<<(2*CC*CC)/1024, 256>>>(kv_conv_w, wkvh, wkvl, 2*CC*CC);
    k_cvt<<<(3*CC*CC)/1024, 256>>>(in_proj_w, winh, winl, 3*CC*CC);
    k_cvt<<<(CC*CC)/1024,   256>>>(out_proj_w,woh,  wol,  CC*CC);
    k_cvt<<<(MM*CC)/1024,   256>>>(w1,        w1h,  w1l,  MM*CC);
    k_cvt<<<(CC*MM)/1024,   256>>>(w2,        w2h,  w2l,  CC*MM);

    dim3 tgrid(LL/32, CC/32, BB), tblk(32, 8);
    k_transpose_in<<<tgrid, tblk>>>(x, xt, xth, xtl);

    // Q / KV projections
    k_gemm_mma<<<dim3(CC/256,   BLROWS/128), 256, GS>>>(xth, xtl, wqh,  wql,  q_conv_b,  q,  CC,   CC);
    k_gemm_mma<<<dim3(2*CC/256, BLROWS/128), 256, GS>>>(xth, xtl, wkvh, wkvl, kv_conv_b, kv, 2*CC, CC);

    // LayerNorms (+l2n for Q,K)
    k_ln512<<<BLROWS/8, 256>>>(q,       CC,   q,  q_ln_g, q_ln_b, 1, nullptr, nullptr, qh, ql);
    k_ln512<<<BLROWS/8, 256>>>(kv,      2*CC, kn, k_ln_g, k_ln_b, 1, nullptr, nullptr, nullptr, nullptr);
    k_ln512<<<BLROWS/8, 256>>>(kv + CC, 2*CC, vt, v_ln_g, v_ln_b, 0, nullptr, nullptr, nullptr, nullptr);

    // probe, score, top-k, gather
    k_probe_partial<<<dim3(BB, 32), CC>>>(q, pp);
    k_probe_reduce<<<BB, CC>>>(pp, probe);
    k_score<<<(BB*LL*32)/256, 256>>>(kn, probe, score);
    k_topk<<<BB*HH, 512>>>(score, idx);
    k_gather<<<BB*TK, CC>>>(kn, vt, idx, kch, kcl, vch, vcl);

    // in_proj
    k_gemm_mma<<<dim3(CC/256, BLROWS/128),  256, GS>>>(qh,  ql,  winh,           winl,           in_proj_b,        qp, CC, CC);
    k_gemm_mma<<<dim3(CC/256, (BB*TK)/128), 256, GS>>>(kch, kcl, winh + CC*CC,   winl + CC*CC,   in_proj_b + CC,   kp, CC, CC);
    k_gemm_mma<<<dim3(CC/256, (BB*TK)/128), 256, GS>>>(vch, vcl, winh + 2*CC*CC, winl + 2*CC*CC, in_proj_b + 2*CC, vp, CC, CC);

    // attention (257 keys: 256 selected + bias key) -> bf16 hi/lo
    k_attn<<<dim3(LL/64, BB*HH), 256>>>(qp, kp, vp, bias_k, bias_v, aoh, aol);

    // out_proj -> h2(temp), attn LN * gamma + x residual -> a (+ hi/lo)
    k_gemm_mma<<<dim3(CC/256, BLROWS/128), 256, GS>>>(aoh, aol, woh, wol, out_proj_b, h2, CC, CC);
    k_ln512<<<BLROWS/8, 256>>>(h2, CC, a, attn_ln_g, attn_ln_b, 2, gamma, xt, ah, al);

    // FFN
    k_gemm_mma<<<dim3(MM/256, BLROWS/128), 256, GS>>>(ah, al, w1h, w1l, b1, h1, MM, CC);
    k_ln2048<<<BLROWS/8, 256>>>(h1, n1_g, n1_b, h1h, h1l);
    k_gemm_mma<<<dim3(CC/256, BLROWS/128), 256, GS>>>(h1h, h1l, w2h, w2l, b2, h2, CC, MM);
    k_ln512<<<BLROWS/8, 256>>>(h2, CC, h2, n2_g, n2_b, 3, nullptr, nullptr, nullptr, nullptr);

    // out = transpose(h2 + a)
    k_add_transpose_out<<<tgrid, tblk>>>(h2, a, out);
}